// round 11
// baseline (speedup 1.0000x reference)
#include <cuda_runtime.h>
#include <cuda_bf16.h>
#include <cstdint>

// ---------------------------------------------------------------------------
// ConditionalRealNVP log_prob — R10: split-N warp pairs.
// 512 threads / 16 warps, each warp owns 32 rows x 64 cols of its net
// (dual-M => every B fragment feeds 2 m16 tiles => B-LDSM halves vs R7),
// warp pairs (w, w^1) exchange hid1 halves through smem (phased staging,
// ldmatrix-compatible layout) so GEMM2 gets full K=128.
// GEMM3 is split-K with 4 partial slots summed in the final epilogue.
// ---------------------------------------------------------------------------

#define BTOT   524288
#define MTILE  128
#define NTILES (BTOT / MTILE)   // 4096
#define XP_LD  88
#define W_LD   264
#define W3_LD  16
#define NTHREADS 512
#define XP_BYTES (128 * XP_LD * 2)   // 22528
#define SH_LD  528                   // hid1 staging row stride (bytes)

// smem byte offsets
#define OFF_W1  0                  // 66*264*2  = 34848
#define OFF_W2  34848              // 128*264*2 = 67584
#define OFF_W3  102432             // 128*16*2  = 4096
#define OFF_XP  106528             // 2 x 22528 = 45056
#define OFF_XA  151584             // 2 x 2048  = 4096
#define OFF_B1  155680             // 1024
#define OFF_B2  156704             // 1024
#define OFF_B3  157728             // 32
#define OFF_ST  157760             // 4 slots x 2 net x 128 x 2 f32 = 8192
#define OFF_SH  165952             // 64 rows x 528 = 33792
#define SMEM_BYTES 199744

__device__ float g_x[BTOT * 4];
__device__ float g_ld[BTOT];
__device__ __nv_bfloat16 g_hbf[(long)BTOT * 64];

__device__ __forceinline__ uint32_t smem_u32(const void* p) {
    return static_cast<uint32_t>(__cvta_generic_to_shared(p));
}
__device__ __forceinline__ void cp_async16(uint32_t dst, const void* src) {
    asm volatile("cp.async.cg.shared.global [%0], [%1], 16;"
                 :: "r"(dst), "l"(src) : "memory");
}
#define CP_COMMIT() asm volatile("cp.async.commit_group;" ::: "memory")
#define CP_WAIT0()  asm volatile("cp.async.wait_group 0;" ::: "memory")

__device__ __forceinline__ void ldsm_x4(uint32_t a, uint32_t& r0, uint32_t& r1,
                                        uint32_t& r2, uint32_t& r3) {
    asm volatile("ldmatrix.sync.aligned.m8n8.x4.shared.b16 {%0,%1,%2,%3},[%4];"
                 : "=r"(r0), "=r"(r1), "=r"(r2), "=r"(r3) : "r"(a));
}
__device__ __forceinline__ void ldsm_x4t(uint32_t a, uint32_t& r0, uint32_t& r1,
                                         uint32_t& r2, uint32_t& r3) {
    asm volatile("ldmatrix.sync.aligned.m8n8.x4.trans.shared.b16 {%0,%1,%2,%3},[%4];"
                 : "=r"(r0), "=r"(r1), "=r"(r2), "=r"(r3) : "r"(a));
}
__device__ __forceinline__ void ldsm_x2t(uint32_t a, uint32_t& r0, uint32_t& r1) {
    asm volatile("ldmatrix.sync.aligned.m8n8.x2.trans.shared.b16 {%0,%1},[%2];"
                 : "=r"(r0), "=r"(r1) : "r"(a));
}
__device__ __forceinline__ void mma_bf16(float* c, const uint32_t* a,
                                         uint32_t b0, uint32_t b1) {
    asm volatile(
        "mma.sync.aligned.m16n8k16.row.col.f32.bf16.bf16.f32 "
        "{%0,%1,%2,%3},{%4,%5,%6,%7},{%8,%9},{%0,%1,%2,%3};"
        : "+f"(c[0]), "+f"(c[1]), "+f"(c[2]), "+f"(c[3])
        : "r"(a[0]), "r"(a[1]), "r"(a[2]), "r"(a[3]), "r"(b0), "r"(b1));
}
__device__ __forceinline__ uint32_t pack_bf2(float lo, float hi) {
    __nv_bfloat162 v = __floats2bfloat162_rn(lo, hi);
    return *reinterpret_cast<uint32_t*>(&v);
}
// packed bf16x2 tanh-approx GELU
__device__ __forceinline__ uint32_t gelu2(uint32_t xin) {
    __nv_bfloat162 x = *reinterpret_cast<__nv_bfloat162*>(&xin);
    const __nv_bfloat162 c1 = __floats2bfloat162_rn(0.035677408136f, 0.035677408136f);
    const __nv_bfloat162 c0 = __floats2bfloat162_rn(0.7978845608028654f, 0.7978845608028654f);
    const __nv_bfloat162 hf = __floats2bfloat162_rn(0.5f, 0.5f);
    __nv_bfloat162 x2 = __hmul2(x, x);
    __nv_bfloat162 w  = __hfma2(x2, c1, c0);
    __nv_bfloat162 u  = __hmul2(x, w);
    uint32_t th;
    asm("tanh.approx.bf16x2 %0, %1;"
        : "=r"(th) : "r"(*reinterpret_cast<uint32_t*>(&u)));
    __nv_bfloat162 hx = __hmul2(x, hf);
    __nv_bfloat162 r  = __hfma2(hx, *reinterpret_cast<__nv_bfloat162*>(&th), hx);
    return *reinterpret_cast<uint32_t*>(&r);
}

// ---- pre-pass: h fp32 -> bf16 (run once per graph replay) ----
__global__ void __launch_bounds__(256)
cvt_h_kernel(const float* __restrict__ h) {
    long i = ((long)blockIdx.x * 256 + threadIdx.x) * 8;
    float4 a = *reinterpret_cast<const float4*>(h + i);
    float4 b = *reinterpret_cast<const float4*>(h + i + 4);
    uint4 o;
    o.x = pack_bf2(a.x, a.y); o.y = pack_bf2(a.z, a.w);
    o.z = pack_bf2(b.x, b.y); o.w = pack_bf2(b.z, b.w);
    *reinterpret_cast<uint4*>(g_hbf + i) = o;
}

template <int LYR>
__global__ void __launch_bounds__(NTHREADS, 1)
nvp_layer(const float* __restrict__ theta, const float* __restrict__ h,
          const float* __restrict__ w1s, const float* __restrict__ b1s,
          const float* __restrict__ w2s, const float* __restrict__ b2s,
          const float* __restrict__ w3s, const float* __restrict__ b3s,
          const float* __restrict__ w1t, const float* __restrict__ b1t,
          const float* __restrict__ w2t, const float* __restrict__ b2t,
          const float* __restrict__ w3t, const float* __restrict__ b3t,
          float* __restrict__ out)
{
    constexpr bool FIRST = (LYR == 0);
    constexpr bool LAST  = (LYR == 3);
    // KEEP = ((0,1),(1,2),(2,3),(0,3)); TRANS = ((2,3),(0,3),(0,1),(1,2))
    constexpr int K0 = (LYR == 0) ? 0 : (LYR == 1) ? 1 : (LYR == 2) ? 2 : 0;
    constexpr int K1 = (LYR == 0) ? 1 : (LYR == 1) ? 2 : (LYR == 2) ? 3 : 3;
    constexpr int T0 = (LYR == 0) ? 2 : (LYR == 1) ? 0 : (LYR == 2) ? 0 : 1;
    constexpr int T1 = (LYR == 0) ? 3 : (LYR == 1) ? 3 : (LYR == 2) ? 1 : 2;

    extern __shared__ char smem[];
    const uint32_t smem_base = smem_u32(smem);
    __nv_bfloat16* sW1 = reinterpret_cast<__nv_bfloat16*>(smem + OFF_W1);
    __nv_bfloat16* sW2 = reinterpret_cast<__nv_bfloat16*>(smem + OFF_W2);
    __nv_bfloat16* sW3 = reinterpret_cast<__nv_bfloat16*>(smem + OFF_W3);
    float* sB1 = reinterpret_cast<float*>(smem + OFF_B1);
    float* sB2 = reinterpret_cast<float*>(smem + OFF_B2);
    float* sB3 = reinterpret_cast<float*>(smem + OFF_B3);
    float* sST = reinterpret_cast<float*>(smem + OFF_ST);

    const int tid = threadIdx.x;

    // ---- one-time weights -> smem ----
    // W1: 66 rows only. Rows 0..63 = w1[k+2] (h part), 64..65 = w1[0..1].
    // The k-pad ldsm (rows 66..79) reads into the W2 region: finite garbage
    // multiplied by zeroed xp pad columns => exact zeros.
    for (int idx = tid; idx < 66 * W_LD; idx += NTHREADS) {
        int k = idx / W_LD, c = idx - k * W_LD;
        float v = 0.0f;
        if (c < 256) {
            const float* w1 = (c < 128) ? w1s : w1t;
            int cc = c & 127;
            if (k < 64) v = w1[(k + 2) * 128 + cc];
            else        v = w1[(k - 64) * 128 + cc];
        }
        sW1[idx] = __float2bfloat16(v);
    }
    for (int idx = tid; idx < 128 * W_LD; idx += NTHREADS) {
        int k = idx / W_LD, c = idx - k * W_LD;
        float v = 0.0f;
        if (c < 256) v = (c < 128) ? w2s[k * 128 + c] : w2t[k * 128 + c - 128];
        sW2[idx] = __float2bfloat16(v);
    }
    for (int idx = tid; idx < 128 * W3_LD; idx += NTHREADS) {
        int k = idx >> 4, c = idx & 15;
        float v = 0.0f;
        if (c < 2) v = w3s[k * 2 + c];
        else if (c >= 8 && c < 10) v = w3t[k * 2 + c - 8];
        sW3[idx] = __float2bfloat16(v);
    }
    for (int c = tid; c < 256; c += NTHREADS) {
        sB1[c] = (c < 128) ? b1s[c] : b1t[c - 128];
        sB2[c] = (c < 128) ? b2s[c] : b2t[c - 128];
    }
    if (tid < 4) sB3[tid] = (tid < 2) ? b3s[tid] : b3t[tid - 2];
    // zero xp pad cols [66,88) in BOTH buffers (never rewritten)
    for (int idx = tid; idx < 2 * 128 * 22; idx += NTHREADS) {
        int bufr = idx / 22, c = 66 + (idx - bufr * 22);
        int bb = bufr >> 7, r = bufr & 127;
        *reinterpret_cast<__nv_bfloat16*>(
            smem + OFF_XP + bb * XP_BYTES + (r * XP_LD + c) * 2) =
            __float2bfloat16(0.0f);
    }

    const int warp = tid >> 5;
    const int lane = tid & 31;
    const int net  = warp >> 3;           // 0 = s-net, 1 = t-net
    const int w3i  = warp & 7;
    const int rb   = w3i >> 1;            // rowblock 0..3 (32 rows)
    const int ch   = w3i & 1;             // column half 0..1
    const int pch  = ch ^ 1;
    const int R0   = rb * 32;
    const int lg   = lane >> 3;
    const int lr   = lane & 7;
    const int lr0  = lane >> 2;
    const int q2   = (lane & 3) * 2;
    const int cbase = net * 128 + ch * 64;

    // ---- prologue: prefetch tile0 into buf 0 ----
    const int tile0 = blockIdx.x;
    {
        const __nv_bfloat16* hsrc = g_hbf + (long)tile0 * MTILE * 64;
        uint32_t xpn = smem_base + OFF_XP;
        #pragma unroll
        for (int c = tid; c < 1024; c += NTHREADS) {
            int r = c >> 3, q = c & 7;
            cp_async16(xpn + r * 176 + q * 16, hsrc + r * 64 + q * 8);
        }
        if (tid < 128) {
            const float* xsrc = FIRST ? (theta + (long)(tile0 * MTILE + tid) * 4)
                                      : (g_x + (long)(tile0 * MTILE + tid) * 4);
            cp_async16(smem_base + OFF_XA + tid * 16, xsrc);
        }
        CP_COMMIT();
        CP_WAIT0();
        if (tid < 128) {
            float4 nx = *reinterpret_cast<float4*>(smem + OFF_XA + tid * 16);
            float c4[4] = {nx.x, nx.y, nx.z, nx.w};
            *reinterpret_cast<__nv_bfloat162*>(smem + OFF_XP + tid * 176 + 128) =
                __floats2bfloat162_rn(c4[K0], c4[K1]);
        }
    }
    __syncthreads();

    int buf = 0;
    for (int tile = tile0; tile < NTILES; tile += gridDim.x) {
        const int base = tile * MTILE;
        const int nt = tile + gridDim.x;
        const bool has_next = (nt < NTILES);

        // ---- prefetch next tile into buf^1 ----
        if (has_next) {
            const __nv_bfloat16* hsrc = g_hbf + (long)nt * MTILE * 64;
            uint32_t xpn = smem_base + OFF_XP + (buf ^ 1) * XP_BYTES;
            #pragma unroll
            for (int c = tid; c < 1024; c += NTHREADS) {
                int r = c >> 3, q = c & 7;
                cp_async16(xpn + r * 176 + q * 16, hsrc + r * 64 + q * 8);
            }
            if (tid < 128) {
                const float* xsrc = FIRST ? (theta + (long)(nt * MTILE + tid) * 4)
                                          : (g_x + (long)(nt * MTILE + tid) * 4);
                cp_async16(smem_base + OFF_XA + (buf ^ 1) * 2048 + tid * 16, xsrc);
            }
            CP_COMMIT();
        }

        __nv_bfloat16* sXP = reinterpret_cast<__nv_bfloat16*>(
            smem + OFF_XP + buf * XP_BYTES);

        // ---- GEMM1 A frags (K=80), both m-tiles ----
        uint32_t axp[2][5][4];
        #pragma unroll
        for (int mt = 0; mt < 2; mt++) {
            int row = R0 + mt * 16 + lr + (lg & 1) * 8;
            const __nv_bfloat16* pbase = &sXP[row * XP_LD + (lg >> 1) * 8];
            #pragma unroll
            for (int ks = 0; ks < 5; ks++)
                ldsm_x4(smem_u32(pbase + ks * 16), axp[mt][ks][0],
                        axp[mt][ks][1], axp[mt][ks][2], axp[mt][ks][3]);
        }

        // ---- GEMM1: out = hid1[32r x 64c], n32 chunks ----
        uint32_t hfr[2][4][4];
        #pragma unroll
        for (int nq = 0; nq < 2; nq++) {
            float acc[2][4][4];
            #pragma unroll
            for (int j = 0; j < 4; j++) {
                int c = cbase + nq * 32 + j * 8 + q2;
                float2 bb = *reinterpret_cast<const float2*>(&sB1[c]);
                acc[0][j][0] = bb.x; acc[0][j][1] = bb.y;
                acc[0][j][2] = bb.x; acc[0][j][3] = bb.y;
                acc[1][j][0] = bb.x; acc[1][j][1] = bb.y;
                acc[1][j][2] = bb.x; acc[1][j][3] = bb.y;
            }
            const __nv_bfloat16* wb =
                &sW1[(lr + (lg & 1) * 8) * W_LD + cbase + nq * 32 + (lg >> 1) * 8];
            #pragma unroll
            for (int ks = 0; ks < 5; ks++) {
                uint32_t b0, b1, b2, b3, b4, b5, b6, b7;
                ldsm_x4t(smem_u32(wb + ks * 16 * W_LD),      b0, b1, b2, b3);
                ldsm_x4t(smem_u32(wb + ks * 16 * W_LD + 16), b4, b5, b6, b7);
                #pragma unroll
                for (int mt = 0; mt < 2; mt++) {
                    mma_bf16(acc[mt][0], axp[mt][ks], b0, b1);
                    mma_bf16(acc[mt][1], axp[mt][ks], b2, b3);
                    mma_bf16(acc[mt][2], axp[mt][ks], b4, b5);
                    mma_bf16(acc[mt][3], axp[mt][ks], b6, b7);
                }
            }
            #pragma unroll
            for (int mt = 0; mt < 2; mt++) {
                #pragma unroll
                for (int p = 0; p < 2; p++) {
                    int kf = nq * 2 + p;
                    hfr[mt][kf][0] = gelu2(pack_bf2(acc[mt][2 * p][0], acc[mt][2 * p][1]));
                    hfr[mt][kf][1] = gelu2(pack_bf2(acc[mt][2 * p][2], acc[mt][2 * p][3]));
                    hfr[mt][kf][2] = gelu2(pack_bf2(acc[mt][2 * p + 1][0], acc[mt][2 * p + 1][1]));
                    hfr[mt][kf][3] = gelu2(pack_bf2(acc[mt][2 * p + 1][2], acc[mt][2 * p + 1][3]));
                }
            }
        }

        // ---- hid1 exchange, phased by m-tile (32KB staging region) ----
        uint32_t pf[2][4][4];
        #pragma unroll
        for (int mt = 0; mt < 2; mt++) {
            // store own half: reg k of frag kf = (row lr0+(k&1)*8, kcol kf*16+(k>>1)*8+q2)
            #pragma unroll
            for (int kf = 0; kf < 4; kf++) {
                #pragma unroll
                for (int k = 0; k < 4; k++) {
                    int row_s = rb * 16 + lr0 + (k & 1) * 8;
                    int colb = (cbase + kf * 16 + (k >> 1) * 8 + q2) * 2;
                    *reinterpret_cast<uint32_t*>(
                        smem + OFF_SH + row_s * SH_LD + colb) = hfr[mt][kf][k];
                }
            }
            __syncthreads();
            // load partner half (ldmatrix A-frag pattern)
            uint32_t pbase = smem_base + OFF_SH + (rb * 16 + (lane & 15)) * SH_LD
                           + (net * 128 + pch * 64 + (lane >> 4) * 8) * 2;
            #pragma unroll
            for (int kf = 0; kf < 4; kf++)
                ldsm_x4(pbase + kf * 32, pf[mt][kf][0], pf[mt][kf][1],
                        pf[mt][kf][2], pf[mt][kf][3]);
            __syncthreads();
        }

        // ---- GEMM2 (K=128: own half from hfr, partner half from pf) ----
        #pragma unroll
        for (int nq = 0; nq < 2; nq++) {
            float acc[2][4][4];
            #pragma unroll
            for (int j = 0; j < 4; j++) {
                int c = cbase + nq * 32 + j * 8 + q2;
                float2 bb = *reinterpret_cast<const float2*>(&sB2[c]);
                acc[0][j][0] = bb.x; acc[0][j][1] = bb.y;
                acc[0][j][2] = bb.x; acc[0][j][3] = bb.y;
                acc[1][j][0] = bb.x; acc[1][j][1] = bb.y;
                acc[1][j][2] = bb.x; acc[1][j][3] = bb.y;
            }
            const __nv_bfloat16* wb2 =
                &sW2[(lr + (lg & 1) * 8) * W_LD + cbase + nq * 32 + (lg >> 1) * 8];
            // own K half (rows ch*64 ..)
            #pragma unroll
            for (int kk = 0; kk < 4; kk++) {
                const __nv_bfloat16* wr = wb2 + (ch * 64 + kk * 16) * W_LD;
                uint32_t b0, b1, b2, b3, b4, b5, b6, b7;
                ldsm_x4t(smem_u32(wr),      b0, b1, b2, b3);
                ldsm_x4t(smem_u32(wr + 16), b4, b5, b6, b7);
                #pragma unroll
                for (int mt = 0; mt < 2; mt++) {
                    mma_bf16(acc[mt][0], hfr[mt][kk], b0, b1);
                    mma_bf16(acc[mt][1], hfr[mt][kk], b2, b3);
                    mma_bf16(acc[mt][2], hfr[mt][kk], b4, b5);
                    mma_bf16(acc[mt][3], hfr[mt][kk], b6, b7);
                }
            }
            // partner K half (rows pch*64 ..)
            #pragma unroll
            for (int kk = 0; kk < 4; kk++) {
                const __nv_bfloat16* wr = wb2 + (pch * 64 + kk * 16) * W_LD;
                uint32_t b0, b1, b2, b3, b4, b5, b6, b7;
                ldsm_x4t(smem_u32(wr),      b0, b1, b2, b3);
                ldsm_x4t(smem_u32(wr + 16), b4, b5, b6, b7);
                #pragma unroll
                for (int mt = 0; mt < 2; mt++) {
                    mma_bf16(acc[mt][0], pf[mt][kk], b0, b1);
                    mma_bf16(acc[mt][1], pf[mt][kk], b2, b3);
                    mma_bf16(acc[mt][2], pf[mt][kk], b4, b5);
                    mma_bf16(acc[mt][3], pf[mt][kk], b6, b7);
                }
            }
            // epi2 + GEMM3 partial (K = this warp's hid2 cols)
            uint32_t af[2][2][4];
            #pragma unroll
            for (int mt = 0; mt < 2; mt++) {
                #pragma unroll
                for (int p = 0; p < 2; p++) {
                    af[mt][p][0] = gelu2(pack_bf2(acc[mt][2 * p][0], acc[mt][2 * p][1]));
                    af[mt][p][1] = gelu2(pack_bf2(acc[mt][2 * p][2], acc[mt][2 * p][3]));
                    af[mt][p][2] = gelu2(pack_bf2(acc[mt][2 * p + 1][0], acc[mt][2 * p + 1][1]));
                    af[mt][p][3] = gelu2(pack_bf2(acc[mt][2 * p + 1][2], acc[mt][2 * p + 1][3]));
                }
            }
            float acc3[2][4] = {{0.f, 0.f, 0.f, 0.f}, {0.f, 0.f, 0.f, 0.f}};
            #pragma unroll
            for (int p = 0; p < 2; p++) {
                int krow = ch * 64 + nq * 32 + p * 16;
                uint32_t addr = smem_u32(&sW3[(krow + (lane & 15)) * W3_LD + net * 8]);
                uint32_t w0, w1r;
                ldsm_x2t(addr, w0, w1r);
                mma_bf16(acc3[0], af[0][p], w0, w1r);
                mma_bf16(acc3[1], af[1][p], w0, w1r);
            }
            // stage partials: slot = ch*2 + nq
            if ((lane & 3) == 0) {
                int slot = ch * 2 + nq;
                int r1 = lane >> 2;
                #pragma unroll
                for (int mt = 0; mt < 2; mt++) {
                    #pragma unroll
                    for (int half = 0; half < 2; half++) {
                        int row = R0 + mt * 16 + r1 + half * 8;
                        int idx = ((slot * 2 + net) * 128 + row) * 2;
                        sST[idx + 0] = acc3[mt][half * 2 + 0];
                        sST[idx + 1] = acc3[mt][half * 2 + 1];
                    }
                }
            }
        }

        // current-tile x into regs (sXA[buf] final since last iteration)
        float4 xv = make_float4(0.f, 0.f, 0.f, 0.f);
        if (tid < 128)
            xv = *reinterpret_cast<float4*>(smem + OFF_XA + buf * 2048 + tid * 16);

        // finish next-tile prefetch: wait + x-keep conversion into xp[buf^1]
        if (has_next) {
            CP_WAIT0();
            if (tid < 128) {
                float4 nx = *reinterpret_cast<float4*>(
                    smem + OFF_XA + (buf ^ 1) * 2048 + tid * 16);
                float c4[4] = {nx.x, nx.y, nx.z, nx.w};
                *reinterpret_cast<__nv_bfloat162*>(
                    smem + OFF_XP + (buf ^ 1) * XP_BYTES + tid * 176 + 128) =
                    __floats2bfloat162_rn(c4[K0], c4[K1]);
            }
        }
        __syncthreads();

        // ---- epilogue: one thread per row; sum the 4 split-K slots ----
        if (tid < 128) {
            int row = tid;
            int b = base + row;
            float s0 = sB3[0], s1 = sB3[1], t0 = sB3[2], t1 = sB3[3];
            #pragma unroll
            for (int slot = 0; slot < 4; slot++) {
                int is = ((slot * 2 + 0) * 128 + row) * 2;
                int it = ((slot * 2 + 1) * 128 + row) * 2;
                s0 += sST[is + 0]; s1 += sST[is + 1];
                t0 += sST[it + 0]; t1 += sST[it + 1];
            }
            float xc[4] = {xv.x, xv.y, xv.z, xv.w};
            float nx0 = xc[T0] * __expf(s0) + t0;
            float nx1 = xc[T1] * __expf(s1) + t1;
            float ld = s0 + s1;
            if (!FIRST) ld += g_ld[b];
            xc[T0] = nx0;
            xc[T1] = nx1;
            if (!LAST) {
                reinterpret_cast<float4*>(g_x)[b] =
                    make_float4(xc[0], xc[1], xc[2], xc[3]);
                g_ld[b] = ld;
            } else {
                float ss = xc[0] * xc[0] + xc[1] * xc[1] +
                           xc[2] * xc[2] + xc[3] * xc[3];
                out[b] = -0.5f * ss - 3.6757541328186907f + ld;
            }
        }
        buf ^= 1;
    }
}

extern "C" void kernel_launch(void* const* d_in, const int* in_sizes, int n_in,
                              void* d_out, int out_size)
{
    const float* theta = (const float*)d_in[0];
    const float* h     = (const float*)d_in[1];
    const float* sW1   = (const float*)d_in[2];
    const float* sb1   = (const float*)d_in[3];
    const float* sW2   = (const float*)d_in[4];
    const float* sb2   = (const float*)d_in[5];
    const float* sW3   = (const float*)d_in[6];
    const float* sb3   = (const float*)d_in[7];
    const float* tW1   = (const float*)d_in[8];
    const float* tb1   = (const float*)d_in[9];
    const float* tW2   = (const float*)d_in[10];
    const float* tb2   = (const float*)d_in[11];
    const float* tW3   = (const float*)d_in[12];
    const float* tb3   = (const float*)d_in[13];
    float* out = (float*)d_out;

    int nsm = 148;
    cudaDeviceGetAttribute(&nsm, cudaDevAttrMultiProcessorCount, 0);

    cudaFuncSetAttribute(nvp_layer<0>, cudaFuncAttributeMaxDynamicSharedMemorySize, SMEM_BYTES);
    cudaFuncSetAttribute(nvp_layer<1>, cudaFuncAttributeMaxDynamicSharedMemorySize, SMEM_BYTES);
    cudaFuncSetAttribute(nvp_layer<2>, cudaFuncAttributeMaxDynamicSharedMemorySize, SMEM_BYTES);
    cudaFuncSetAttribute(nvp_layer<3>, cudaFuncAttributeMaxDynamicSharedMemorySize, SMEM_BYTES);

    // pre-pass: h -> bf16 (BTOT*64 elems, 8 per thread, 256 threads/block)
    cvt_h_kernel<<<(BTOT * 64) / (8 * 256), 256>>>(h);

    dim3 grid(nsm), blk(NTHREADS);
    #define ARGS(L) theta, h,                                        \
        sW1 + (L) * 66 * 128, sb1 + (L) * 128,                       \
        sW2 + (L) * 128 * 128, sb2 + (L) * 128,                      \
        sW3 + (L) * 128 * 2, sb3 + (L) * 2,                          \
        tW1 + (L) * 66 * 128, tb1 + (L) * 128,                       \
        tW2 + (L) * 128 * 128, tb2 + (L) * 128,                      \
        tW3 + (L) * 128 * 2, tb3 + (L) * 2, out

    nvp_layer<0><<<grid, blk, SMEM_BYTES>>>(ARGS(0));
    nvp_layer<1><<<grid, blk, SMEM_BYTES>>>(ARGS(1));
    nvp_layer<2><<<grid, blk, SMEM_BYTES>>>(ARGS(2));
    nvp_layer<3><<<grid, blk, SMEM_BYTES>>>(ARGS(3));
    #undef ARGS
}

// round 12
// speedup vs baseline: 1.0381x; 1.0381x over previous
#include <cuda_runtime.h>
#include <cuda_bf16.h>
#include <cstdint>

// ---------------------------------------------------------------------------
// ConditionalRealNVP log_prob — R11: dual-tile M-doubling at 16 warps.
// Each iteration processes a PAIR of 128-row tiles; every warp computes its
// 16 rows in BOTH tiles so each B fragment feeds two m16 MMAs (B-LDSM per
// row halves vs R7) while occupancy stays 25% (512 thr, regs <= 128 via
// N=32 chunking: GEMM1 reloads A per chunk, GEMM2 holds hid1 in regs).
// One __syncthreads per iteration, cp.async double-buffered pair prefetch.
// ---------------------------------------------------------------------------

#define BTOT   524288
#define NPAIRS (BTOT / 256)     // 2048
#define XP_LD  88
#define W_LD   264
#define W3_LD  16
#define NTHREADS 512
#define XP_T   22528            // one tile's xp bytes (128*88*2)
#define XP_P   45056            // one buffer (pair) = 2 tiles

// smem byte offsets
#define OFF_W1  0               // 80*264*2  = 42240
#define OFF_W2  42240           // 128*264*2 = 67584
#define OFF_W3  109824          // 128*16*2  = 4096
#define OFF_XP  113920          // 2 buf x 45056 = 90112
#define OFF_XA  204032          // 2 buf x 4096  = 8192
#define OFF_B1  212224          // 1024
#define OFF_B2  213248          // 1024
#define OFF_B3  214272          // 32
#define OFF_ST  214304          // 2 buf x 4096  = 8192
#define SMEM_BYTES 222496

__device__ float g_x[BTOT * 4];
__device__ float g_ld[BTOT];
__device__ __nv_bfloat16 g_hbf[(long)BTOT * 64];

__device__ __forceinline__ uint32_t smem_u32(const void* p) {
    return static_cast<uint32_t>(__cvta_generic_to_shared(p));
}
__device__ __forceinline__ void cp_async16(uint32_t dst, const void* src) {
    asm volatile("cp.async.cg.shared.global [%0], [%1], 16;"
                 :: "r"(dst), "l"(src) : "memory");
}
#define CP_COMMIT() asm volatile("cp.async.commit_group;" ::: "memory")
#define CP_WAIT0()  asm volatile("cp.async.wait_group 0;" ::: "memory")

__device__ __forceinline__ void ldsm_x4(uint32_t a, uint32_t& r0, uint32_t& r1,
                                        uint32_t& r2, uint32_t& r3) {
    asm volatile("ldmatrix.sync.aligned.m8n8.x4.shared.b16 {%0,%1,%2,%3},[%4];"
                 : "=r"(r0), "=r"(r1), "=r"(r2), "=r"(r3) : "r"(a));
}
__device__ __forceinline__ void ldsm_x4t(uint32_t a, uint32_t& r0, uint32_t& r1,
                                         uint32_t& r2, uint32_t& r3) {
    asm volatile("ldmatrix.sync.aligned.m8n8.x4.trans.shared.b16 {%0,%1,%2,%3},[%4];"
                 : "=r"(r0), "=r"(r1), "=r"(r2), "=r"(r3) : "r"(a));
}
__device__ __forceinline__ void ldsm_x2t(uint32_t a, uint32_t& r0, uint32_t& r1) {
    asm volatile("ldmatrix.sync.aligned.m8n8.x2.trans.shared.b16 {%0,%1},[%2];"
                 : "=r"(r0), "=r"(r1) : "r"(a));
}
__device__ __forceinline__ void mma_bf16(float* c, const uint32_t* a,
                                         uint32_t b0, uint32_t b1) {
    asm volatile(
        "mma.sync.aligned.m16n8k16.row.col.f32.bf16.bf16.f32 "
        "{%0,%1,%2,%3},{%4,%5,%6,%7},{%8,%9},{%0,%1,%2,%3};"
        : "+f"(c[0]), "+f"(c[1]), "+f"(c[2]), "+f"(c[3])
        : "r"(a[0]), "r"(a[1]), "r"(a[2]), "r"(a[3]), "r"(b0), "r"(b1));
}
__device__ __forceinline__ uint32_t pack_bf2(float lo, float hi) {
    __nv_bfloat162 v = __floats2bfloat162_rn(lo, hi);
    return *reinterpret_cast<uint32_t*>(&v);
}
// packed bf16x2 tanh-approx GELU
__device__ __forceinline__ uint32_t gelu2(uint32_t xin) {
    __nv_bfloat162 x = *reinterpret_cast<__nv_bfloat162*>(&xin);
    const __nv_bfloat162 c1 = __floats2bfloat162_rn(0.035677408136f, 0.035677408136f);
    const __nv_bfloat162 c0 = __floats2bfloat162_rn(0.7978845608028654f, 0.7978845608028654f);
    const __nv_bfloat162 hf = __floats2bfloat162_rn(0.5f, 0.5f);
    __nv_bfloat162 x2 = __hmul2(x, x);
    __nv_bfloat162 w  = __hfma2(x2, c1, c0);
    __nv_bfloat162 u  = __hmul2(x, w);
    uint32_t th;
    asm("tanh.approx.bf16x2 %0, %1;"
        : "=r"(th) : "r"(*reinterpret_cast<uint32_t*>(&u)));
    __nv_bfloat162 hx = __hmul2(x, hf);
    __nv_bfloat162 r  = __hfma2(hx, *reinterpret_cast<__nv_bfloat162*>(&th), hx);
    return *reinterpret_cast<uint32_t*>(&r);
}

// ---- pre-pass: h fp32 -> bf16 (run once per graph replay) ----
__global__ void __launch_bounds__(256)
cvt_h_kernel(const float* __restrict__ h) {
    long i = ((long)blockIdx.x * 256 + threadIdx.x) * 8;
    float4 a = *reinterpret_cast<const float4*>(h + i);
    float4 b = *reinterpret_cast<const float4*>(h + i + 4);
    uint4 o;
    o.x = pack_bf2(a.x, a.y); o.y = pack_bf2(a.z, a.w);
    o.z = pack_bf2(b.x, b.y); o.w = pack_bf2(b.z, b.w);
    *reinterpret_cast<uint4*>(g_hbf + i) = o;
}

template <int LYR>
__global__ void __launch_bounds__(NTHREADS, 1)
nvp_layer(const float* __restrict__ theta, const float* __restrict__ h,
          const float* __restrict__ w1s, const float* __restrict__ b1s,
          const float* __restrict__ w2s, const float* __restrict__ b2s,
          const float* __restrict__ w3s, const float* __restrict__ b3s,
          const float* __restrict__ w1t, const float* __restrict__ b1t,
          const float* __restrict__ w2t, const float* __restrict__ b2t,
          const float* __restrict__ w3t, const float* __restrict__ b3t,
          float* __restrict__ out)
{
    constexpr bool FIRST = (LYR == 0);
    constexpr bool LAST  = (LYR == 3);
    // KEEP = ((0,1),(1,2),(2,3),(0,3)); TRANS = ((2,3),(0,3),(0,1),(1,2))
    constexpr int K0 = (LYR == 0) ? 0 : (LYR == 1) ? 1 : (LYR == 2) ? 2 : 0;
    constexpr int K1 = (LYR == 0) ? 1 : (LYR == 1) ? 2 : (LYR == 2) ? 3 : 3;
    constexpr int T0 = (LYR == 0) ? 2 : (LYR == 1) ? 0 : (LYR == 2) ? 0 : 1;
    constexpr int T1 = (LYR == 0) ? 3 : (LYR == 1) ? 3 : (LYR == 2) ? 1 : 2;

    extern __shared__ char smem[];
    const uint32_t smem_base = smem_u32(smem);
    __nv_bfloat16* sW1 = reinterpret_cast<__nv_bfloat16*>(smem + OFF_W1);
    __nv_bfloat16* sW2 = reinterpret_cast<__nv_bfloat16*>(smem + OFF_W2);
    __nv_bfloat16* sW3 = reinterpret_cast<__nv_bfloat16*>(smem + OFF_W3);
    float* sB1 = reinterpret_cast<float*>(smem + OFF_B1);
    float* sB2 = reinterpret_cast<float*>(smem + OFF_B2);
    float* sB3 = reinterpret_cast<float*>(smem + OFF_B3);

    const int tid = threadIdx.x;

    // ---- one-time weights -> smem (same layout as R7) ----
    // W1 rows: 0..63 = w1[k+2] (h part), 64..65 = w1[0..1] (x-keep), 66..79 = 0
    for (int idx = tid; idx < 80 * W_LD; idx += NTHREADS) {
        int k = idx / W_LD, c = idx - k * W_LD;
        float v = 0.0f;
        if (c < 256) {
            const float* w1 = (c < 128) ? w1s : w1t;
            int cc = c & 127;
            if (k < 64)      v = w1[(k + 2) * 128 + cc];
            else if (k < 66) v = w1[(k - 64) * 128 + cc];
        }
        sW1[idx] = __float2bfloat16(v);
    }
    for (int idx = tid; idx < 128 * W_LD; idx += NTHREADS) {
        int k = idx / W_LD, c = idx - k * W_LD;
        float v = 0.0f;
        if (c < 256) v = (c < 128) ? w2s[k * 128 + c] : w2t[k * 128 + c - 128];
        sW2[idx] = __float2bfloat16(v);
    }
    for (int idx = tid; idx < 128 * W3_LD; idx += NTHREADS) {
        int k = idx >> 4, c = idx & 15;
        float v = 0.0f;
        if (c < 2) v = w3s[k * 2 + c];
        else if (c >= 8 && c < 10) v = w3t[k * 2 + c - 8];
        sW3[idx] = __float2bfloat16(v);
    }
    for (int c = tid; c < 256; c += NTHREADS) {
        sB1[c] = (c < 128) ? b1s[c] : b1t[c - 128];
        sB2[c] = (c < 128) ? b2s[c] : b2t[c - 128];
    }
    if (tid < 4) sB3[tid] = (tid < 2) ? b3s[tid] : b3t[tid - 2];
    // zero xp pad cols [66,88): 2 buffers x 2 tiles x 128 rows
    for (int idx = tid; idx < 4 * 128 * 22; idx += NTHREADS) {
        int rr = idx / 22, c = 66 + (idx - rr * 22);
        int bb = rr >> 8, tl = (rr >> 7) & 1, r = rr & 127;
        *reinterpret_cast<__nv_bfloat16*>(
            smem + OFF_XP + bb * XP_P + tl * XP_T + (r * XP_LD + c) * 2) =
            __float2bfloat16(0.0f);
    }

    const int warp = tid >> 5;
    const int lane = tid & 31;
    const int net  = warp >> 3;       // 0 = s-net, 1 = t-net
    const int R0   = (warp & 7) * 16; // row block within each tile
    const int lg   = lane >> 3;
    const int lr   = lane & 7;
    const int q2   = (lane & 3) * 2;

    // ---- prologue: prefetch pair0 into buf 0 ----
    const int p0 = blockIdx.x;
    {
        const __nv_bfloat16* hsrc = g_hbf + (long)p0 * 256 * 64;
        #pragma unroll
        for (int c = tid; c < 2048; c += NTHREADS) {
            int r = c >> 3, q = c & 7;
            uint32_t dst = smem_base + OFF_XP + (r >> 7) * XP_T
                         + (r & 127) * 176 + q * 16;
            cp_async16(dst, hsrc + r * 64 + q * 8);
        }
        if (tid < 256) {
            const float* xsrc = FIRST ? (theta + (long)(p0 * 256 + tid) * 4)
                                      : (g_x + (long)(p0 * 256 + tid) * 4);
            cp_async16(smem_base + OFF_XA + tid * 16, xsrc);
        }
        CP_COMMIT();
        CP_WAIT0();
        if (tid < 256) {
            float4 nx = *reinterpret_cast<float4*>(smem + OFF_XA + tid * 16);
            float c4[4] = {nx.x, nx.y, nx.z, nx.w};
            *reinterpret_cast<__nv_bfloat162*>(
                smem + OFF_XP + (tid >> 7) * XP_T + (tid & 127) * 176 + 128) =
                __floats2bfloat162_rn(c4[K0], c4[K1]);
        }
    }
    __syncthreads();

    int buf = 0;
    for (int p = p0; p < NPAIRS; p += gridDim.x) {
        const int base = p * 256;
        const int np = p + gridDim.x;
        const bool has_next = (np < NPAIRS);

        // ---- prefetch next pair into buf^1 ----
        if (has_next) {
            const __nv_bfloat16* hsrc = g_hbf + (long)np * 256 * 64;
            uint32_t xpn = smem_base + OFF_XP + (buf ^ 1) * XP_P;
            #pragma unroll
            for (int c = tid; c < 2048; c += NTHREADS) {
                int r = c >> 3, q = c & 7;
                cp_async16(xpn + (r >> 7) * XP_T + (r & 127) * 176 + q * 16,
                           hsrc + r * 64 + q * 8);
            }
            if (tid < 256) {
                const float* xsrc = FIRST ? (theta + (long)(np * 256 + tid) * 4)
                                          : (g_x + (long)(np * 256 + tid) * 4);
                cp_async16(smem_base + OFF_XA + (buf ^ 1) * 4096 + tid * 16, xsrc);
            }
            CP_COMMIT();
        }

        float* sST = reinterpret_cast<float*>(smem + OFF_ST + buf * 4096);

        // A-frag base addresses for both tiles (same warp rows in each)
        const uint32_t apA = smem_base + OFF_XP + buf * XP_P
                           + (R0 + lr + (lg & 1) * 8) * 176 + (lg >> 1) * 16;
        const uint32_t apB = apA + XP_T;

        // ---- GEMM1 (K=80) in 4 N=32 chunks, dual-tile ----
        uint32_t hfr[2][8][4];
        #pragma unroll
        for (int ch = 0; ch < 4; ch++) {
            float acc[2][4][4];
            #pragma unroll
            for (int j = 0; j < 4; j++) {
                int c = net * 128 + ch * 32 + j * 8 + q2;
                float2 bb = *reinterpret_cast<const float2*>(&sB1[c]);
                acc[0][j][0] = bb.x; acc[0][j][1] = bb.y;
                acc[0][j][2] = bb.x; acc[0][j][3] = bb.y;
                acc[1][j][0] = bb.x; acc[1][j][1] = bb.y;
                acc[1][j][2] = bb.x; acc[1][j][3] = bb.y;
            }
            const __nv_bfloat16* wb =
                &sW1[(lr + (lg & 1) * 8) * W_LD + net * 128 + ch * 32 + (lg >> 1) * 8];
            #pragma unroll
            for (int ks = 0; ks < 5; ks++) {
                uint32_t b0, b1, b2, b3, b4, b5, b6, b7;
                ldsm_x4t(smem_u32(wb + ks * 16 * W_LD),      b0, b1, b2, b3);
                ldsm_x4t(smem_u32(wb + ks * 16 * W_LD + 16), b4, b5, b6, b7);
                uint32_t a0[4], a1[4];
                ldsm_x4(apA + ks * 32, a0[0], a0[1], a0[2], a0[3]);
                ldsm_x4(apB + ks * 32, a1[0], a1[1], a1[2], a1[3]);
                mma_bf16(acc[0][0], a0, b0, b1); mma_bf16(acc[1][0], a1, b0, b1);
                mma_bf16(acc[0][1], a0, b2, b3); mma_bf16(acc[1][1], a1, b2, b3);
                mma_bf16(acc[0][2], a0, b4, b5); mma_bf16(acc[1][2], a1, b4, b5);
                mma_bf16(acc[0][3], a0, b6, b7); mma_bf16(acc[1][3], a1, b6, b7);
            }
            #pragma unroll
            for (int mt = 0; mt < 2; mt++) {
                hfr[mt][ch * 2 + 0][0] = gelu2(pack_bf2(acc[mt][0][0], acc[mt][0][1]));
                hfr[mt][ch * 2 + 0][1] = gelu2(pack_bf2(acc[mt][0][2], acc[mt][0][3]));
                hfr[mt][ch * 2 + 0][2] = gelu2(pack_bf2(acc[mt][1][0], acc[mt][1][1]));
                hfr[mt][ch * 2 + 0][3] = gelu2(pack_bf2(acc[mt][1][2], acc[mt][1][3]));
                hfr[mt][ch * 2 + 1][0] = gelu2(pack_bf2(acc[mt][2][0], acc[mt][2][1]));
                hfr[mt][ch * 2 + 1][1] = gelu2(pack_bf2(acc[mt][2][2], acc[mt][2][3]));
                hfr[mt][ch * 2 + 1][2] = gelu2(pack_bf2(acc[mt][3][0], acc[mt][3][1]));
                hfr[mt][ch * 2 + 1][3] = gelu2(pack_bf2(acc[mt][3][2], acc[mt][3][3]));
            }
        }

        // ---- GEMM2 (K=128) in 4 N=32 chunks, dual-tile; GEMM3 fused ----
        float acc3[2][4] = {{0.f, 0.f, 0.f, 0.f}, {0.f, 0.f, 0.f, 0.f}};
        #pragma unroll
        for (int cq = 0; cq < 4; cq++) {
            float acc[2][4][4];
            #pragma unroll
            for (int j = 0; j < 4; j++) {
                int c = net * 128 + cq * 32 + j * 8 + q2;
                float2 bb = *reinterpret_cast<const float2*>(&sB2[c]);
                acc[0][j][0] = bb.x; acc[0][j][1] = bb.y;
                acc[0][j][2] = bb.x; acc[0][j][3] = bb.y;
                acc[1][j][0] = bb.x; acc[1][j][1] = bb.y;
                acc[1][j][2] = bb.x; acc[1][j][3] = bb.y;
            }
            const __nv_bfloat16* wb2 =
                &sW2[(lr + (lg & 1) * 8) * W_LD + net * 128 + cq * 32 + (lg >> 1) * 8];
            #pragma unroll
            for (int ks = 0; ks < 8; ks++) {
                uint32_t b0, b1, b2, b3, b4, b5, b6, b7;
                ldsm_x4t(smem_u32(wb2 + ks * 16 * W_LD),      b0, b1, b2, b3);
                ldsm_x4t(smem_u32(wb2 + ks * 16 * W_LD + 16), b4, b5, b6, b7);
                const uint32_t* A0 = hfr[0][ks];
                const uint32_t* A1 = hfr[1][ks];
                mma_bf16(acc[0][0], A0, b0, b1); mma_bf16(acc[1][0], A1, b0, b1);
                mma_bf16(acc[0][1], A0, b2, b3); mma_bf16(acc[1][1], A1, b2, b3);
                mma_bf16(acc[0][2], A0, b4, b5); mma_bf16(acc[1][2], A1, b4, b5);
                mma_bf16(acc[0][3], A0, b6, b7); mma_bf16(acc[1][3], A1, b6, b7);
            }
            uint32_t af[2][2][4];
            #pragma unroll
            for (int mt = 0; mt < 2; mt++) {
                af[mt][0][0] = gelu2(pack_bf2(acc[mt][0][0], acc[mt][0][1]));
                af[mt][0][1] = gelu2(pack_bf2(acc[mt][0][2], acc[mt][0][3]));
                af[mt][0][2] = gelu2(pack_bf2(acc[mt][1][0], acc[mt][1][1]));
                af[mt][0][3] = gelu2(pack_bf2(acc[mt][1][2], acc[mt][1][3]));
                af[mt][1][0] = gelu2(pack_bf2(acc[mt][2][0], acc[mt][2][1]));
                af[mt][1][1] = gelu2(pack_bf2(acc[mt][2][2], acc[mt][2][3]));
                af[mt][1][2] = gelu2(pack_bf2(acc[mt][3][0], acc[mt][3][1]));
                af[mt][1][3] = gelu2(pack_bf2(acc[mt][3][2], acc[mt][3][3]));
            }
            // GEMM3 partial: hid2 cols cq*32..+31 (2 k16 frags), W3 shared
            #pragma unroll
            for (int pp = 0; pp < 2; pp++) {
                int krow = cq * 32 + pp * 16;
                uint32_t addr = smem_u32(&sW3[(krow + (lane & 15)) * W3_LD + net * 8]);
                uint32_t w0, w1r;
                ldsm_x2t(addr, w0, w1r);
                mma_bf16(acc3[0], af[0][pp], w0, w1r);
                mma_bf16(acc3[1], af[1][pp], w0, w1r);
            }
        }

        // ---- stage s/t into sST[buf] (per tile) ----
        if ((lane & 3) == 0) {
            int r1 = lane >> 2;
            #pragma unroll
            for (int mt = 0; mt < 2; mt++) {
                #pragma unroll
                for (int half = 0; half < 2; half++) {
                    int row = R0 + r1 + half * 8;
                    int idx = mt * 512 + (net * 128 + row) * 2;
                    sST[idx + 0] = acc3[mt][half * 2 + 0];
                    sST[idx + 1] = acc3[mt][half * 2 + 1];
                }
            }
        }

        // current-pair x into regs (sXA[buf] final since last iteration)
        float4 xv = make_float4(0.f, 0.f, 0.f, 0.f);
        if (tid < 256)
            xv = *reinterpret_cast<float4*>(smem + OFF_XA + buf * 4096 + tid * 16);

        // finish next-pair prefetch: wait + x-keep conversion into xp[buf^1]
        if (has_next) {
            CP_WAIT0();
            if (tid < 256) {
                float4 nx = *reinterpret_cast<float4*>(
                    smem + OFF_XA + (buf ^ 1) * 4096 + tid * 16);
                float c4[4] = {nx.x, nx.y, nx.z, nx.w};
                *reinterpret_cast<__nv_bfloat162*>(
                    smem + OFF_XP + (buf ^ 1) * XP_P + (tid >> 7) * XP_T
                    + (tid & 127) * 176 + 128) =
                    __floats2bfloat162_rn(c4[K0], c4[K1]);
            }
        }
        __syncthreads();

        // ---- epilogue: one thread per row (256 rows) ----
        if (tid < 256) {
            int tl = tid >> 7, row = tid & 127;
            int b = base + tid;
            const float* st = sST + tl * 512;
            float s0 = st[row * 2 + 0] + sB3[0];
            float s1 = st[row * 2 + 1] + sB3[1];
            float t0 = st[(128 + row) * 2 + 0] + sB3[2];
            float t1 = st[(128 + row) * 2 + 1] + sB3[3];
            float xc[4] = {xv.x, xv.y, xv.z, xv.w};
            float nx0 = xc[T0] * __expf(s0) + t0;
            float nx1 = xc[T1] * __expf(s1) + t1;
            float ld = s0 + s1;
            if (!FIRST) ld += g_ld[b];
            xc[T0] = nx0;
            xc[T1] = nx1;
            if (!LAST) {
                reinterpret_cast<float4*>(g_x)[b] =
                    make_float4(xc[0], xc[1], xc[2], xc[3]);
                g_ld[b] = ld;
            } else {
                float ss = xc[0] * xc[0] + xc[1] * xc[1] +
                           xc[2] * xc[2] + xc[3] * xc[3];
                out[b] = -0.5f * ss - 3.6757541328186907f + ld;
            }
        }
        buf ^= 1;
    }
}

extern "C" void kernel_launch(void* const* d_in, const int* in_sizes, int n_in,
                              void* d_out, int out_size)
{
    const float* theta = (const float*)d_in[0];
    const float* h     = (const float*)d_in[1];
    const float* sW1   = (const float*)d_in[2];
    const float* sb1   = (const float*)d_in[3];
    const float* sW2   = (const float*)d_in[4];
    const float* sb2   = (const float*)d_in[5];
    const float* sW3   = (const float*)d_in[6];
    const float* sb3   = (const float*)d_in[7];
    const float* tW1   = (const float*)d_in[8];
    const float* tb1   = (const float*)d_in[9];
    const float* tW2   = (const float*)d_in[10];
    const float* tb2   = (const float*)d_in[11];
    const float* tW3   = (const float*)d_in[12];
    const float* tb3   = (const float*)d_in[13];
    float* out = (float*)d_out;

    int nsm = 148;
    cudaDeviceGetAttribute(&nsm, cudaDevAttrMultiProcessorCount, 0);

    cudaFuncSetAttribute(nvp_layer<0>, cudaFuncAttributeMaxDynamicSharedMemorySize, SMEM_BYTES);
    cudaFuncSetAttribute(nvp_layer<1>, cudaFuncAttributeMaxDynamicSharedMemorySize, SMEM_BYTES);
    cudaFuncSetAttribute(nvp_layer<2>, cudaFuncAttributeMaxDynamicSharedMemorySize, SMEM_BYTES);
    cudaFuncSetAttribute(nvp_layer<3>, cudaFuncAttributeMaxDynamicSharedMemorySize, SMEM_BYTES);

    // pre-pass: h -> bf16 (BTOT*64 elems, 8 per thread, 256 threads/block)
    cvt_h_kernel<<<(BTOT * 64) / (8 * 256), 256>>>(h);

    dim3 grid(nsm), blk(NTHREADS);
    #define ARGS(L) theta, h,                                        \
        sW1 + (L) * 66 * 128, sb1 + (L) * 128,                       \
        sW2 + (L) * 128 * 128, sb2 + (L) * 128,                      \
        sW3 + (L) * 128 * 2, sb3 + (L) * 2,                          \
        tW1 + (L) * 66 * 128, tb1 + (L) * 128,                       \
        tW2 + (L) * 128 * 128, tb2 + (L) * 128,                      \
        tW3 + (L) * 128 * 2, tb3 + (L) * 2, out

    nvp_layer<0><<<grid, blk, SMEM_BYTES>>>(ARGS(0));
    nvp_layer<1><<<grid, blk, SMEM_BYTES>>>(ARGS(1));
    nvp_layer<2><<<grid, blk, SMEM_BYTES>>>(ARGS(2));
    nvp_layer<3><<<grid, blk, SMEM_BYTES>>>(ARGS(3));
    #undef ARGS
}

// round 13
// speedup vs baseline: 1.1893x; 1.1456x over previous
#include <cuda_runtime.h>
#include <cuda_fp16.h>
#include <cstdint>

// ---------------------------------------------------------------------------
// ConditionalRealNVP log_prob — R12: R7 structure with FP16 hidden path.
// mma.sync f16.f16.f16.f16 for GEMM1/GEMM2: the C fragment is already the
// packed half2 pair layout we previously built with cvt packs, so all 64
// pack instructions per warp/tile disappear, bias init halves, and the
// accumulator register footprint halves (scheduling headroom at the 128 cap).
// GEMM3 keeps f32 accumulation. GELU evaluated in half2 (tanh.approx.f16x2).
// ---------------------------------------------------------------------------

#define BTOT   524288
#define MTILE  128
#define NTILES (BTOT / MTILE)   // 4096
#define XP_LD  88
#define W_LD   264
#define W3_LD  16
#define NTHREADS 512
#define XP_BYTES (128 * XP_LD * 2)   // 22528

// smem byte offsets
#define OFF_W1  0                  // 80*264*2  = 42240
#define OFF_W2  42240              // 128*264*2 = 67584
#define OFF_W3  109824             // 128*16*2  = 4096
#define OFF_XP  113920             // 2 x 22528 = 45056
#define OFF_XA  158976             // 2 x 2048  = 4096
#define OFF_B1  163072             // 128*4 (half2 pairs) = 512
#define OFF_B2  163584             // 512
#define OFF_B3  164096             // 32
#define OFF_ST  164128             // 2 x 2048  = 4096
#define SMEM_BYTES 168224

__device__ float g_x[BTOT * 4];
__device__ float g_ld[BTOT];
__device__ __half g_hh[(long)BTOT * 64];

__device__ __forceinline__ uint32_t smem_u32(const void* p) {
    return static_cast<uint32_t>(__cvta_generic_to_shared(p));
}
__device__ __forceinline__ void cp_async16(uint32_t dst, const void* src) {
    asm volatile("cp.async.cg.shared.global [%0], [%1], 16;"
                 :: "r"(dst), "l"(src) : "memory");
}
#define CP_COMMIT() asm volatile("cp.async.commit_group;" ::: "memory")
#define CP_WAIT0()  asm volatile("cp.async.wait_group 0;" ::: "memory")

__device__ __forceinline__ void ldsm_x4(uint32_t a, uint32_t& r0, uint32_t& r1,
                                        uint32_t& r2, uint32_t& r3) {
    asm volatile("ldmatrix.sync.aligned.m8n8.x4.shared.b16 {%0,%1,%2,%3},[%4];"
                 : "=r"(r0), "=r"(r1), "=r"(r2), "=r"(r3) : "r"(a));
}
__device__ __forceinline__ void ldsm_x4t(uint32_t a, uint32_t& r0, uint32_t& r1,
                                         uint32_t& r2, uint32_t& r3) {
    asm volatile("ldmatrix.sync.aligned.m8n8.x4.trans.shared.b16 {%0,%1,%2,%3},[%4];"
                 : "=r"(r0), "=r"(r1), "=r"(r2), "=r"(r3) : "r"(a));
}
__device__ __forceinline__ void ldsm_x2t(uint32_t a, uint32_t& r0, uint32_t& r1) {
    asm volatile("ldmatrix.sync.aligned.m8n8.x2.trans.shared.b16 {%0,%1},[%2];"
                 : "=r"(r0), "=r"(r1) : "r"(a));
}
// f16 x f16 -> f16 accum (C/D packed half2: {row r, row r+8} x colpair)
__device__ __forceinline__ void mma_h(uint32_t& c0, uint32_t& c1,
                                      const uint32_t* a, uint32_t b0, uint32_t b1) {
    asm volatile(
        "mma.sync.aligned.m16n8k16.row.col.f16.f16.f16.f16 "
        "{%0,%1},{%2,%3,%4,%5},{%6,%7},{%0,%1};"
        : "+r"(c0), "+r"(c1)
        : "r"(a[0]), "r"(a[1]), "r"(a[2]), "r"(a[3]), "r"(b0), "r"(b1));
}
// f16 x f16 -> f32 accum (GEMM3)
__device__ __forceinline__ void mma_hf32(float* c, const uint32_t* a,
                                         uint32_t b0, uint32_t b1) {
    asm volatile(
        "mma.sync.aligned.m16n8k16.row.col.f32.f16.f16.f32 "
        "{%0,%1,%2,%3},{%4,%5,%6,%7},{%8,%9},{%0,%1,%2,%3};"
        : "+f"(c[0]), "+f"(c[1]), "+f"(c[2]), "+f"(c[3])
        : "r"(a[0]), "r"(a[1]), "r"(a[2]), "r"(a[3]), "r"(b0), "r"(b1));
}
__device__ __forceinline__ uint32_t pack_h2(float lo, float hi) {
    __half2 v = __floats2half2_rn(lo, hi);
    return *reinterpret_cast<uint32_t*>(&v);
}
// packed half2 tanh-approx GELU: 0.5x(1+tanh(0.79788456*(x+0.044715x^3)))
__device__ __forceinline__ uint32_t gelu2h(uint32_t xin) {
    __half2 x = *reinterpret_cast<__half2*>(&xin);
    const __half2 c1 = __floats2half2_rn(0.035677408136f, 0.035677408136f);
    const __half2 c0 = __floats2half2_rn(0.7978845608028654f, 0.7978845608028654f);
    const __half2 hf = __floats2half2_rn(0.5f, 0.5f);
    __half2 x2 = __hmul2(x, x);
    __half2 w  = __hfma2(x2, c1, c0);
    __half2 u  = __hmul2(x, w);
    uint32_t th;
    asm("tanh.approx.f16x2 %0, %1;"
        : "=r"(th) : "r"(*reinterpret_cast<uint32_t*>(&u)));
    __half2 hx = __hmul2(x, hf);
    __half2 r  = __hfma2(hx, *reinterpret_cast<__half2*>(&th), hx);
    return *reinterpret_cast<uint32_t*>(&r);
}

__device__ __forceinline__ void ldB4(const __half* p, uint32_t bf[4][4]) {
    #pragma unroll
    for (int q = 0; q < 4; q++)
        ldsm_x4t(smem_u32(p + q * 16), bf[q][0], bf[q][1], bf[q][2], bf[q][3]);
}
__device__ __forceinline__ void mma8h(uint32_t acc[8][2], const uint32_t* A,
                                      uint32_t bf[4][4]) {
    #pragma unroll
    for (int q = 0; q < 4; q++) {
        mma_h(acc[2 * q][0],     acc[2 * q][1],     A, bf[q][0], bf[q][1]);
        mma_h(acc[2 * q + 1][0], acc[2 * q + 1][1], A, bf[q][2], bf[q][3]);
    }
}

// ---- pre-pass: h fp32 -> f16 (run once per graph replay) ----
__global__ void __launch_bounds__(256)
cvt_h_kernel(const float* __restrict__ h) {
    long i = ((long)blockIdx.x * 256 + threadIdx.x) * 8;
    float4 a = *reinterpret_cast<const float4*>(h + i);
    float4 b = *reinterpret_cast<const float4*>(h + i + 4);
    uint4 o;
    o.x = pack_h2(a.x, a.y); o.y = pack_h2(a.z, a.w);
    o.z = pack_h2(b.x, b.y); o.w = pack_h2(b.z, b.w);
    *reinterpret_cast<uint4*>(g_hh + i) = o;
}

template <int LYR>
__global__ void __launch_bounds__(NTHREADS, 1)
nvp_layer(const float* __restrict__ theta, const float* __restrict__ h,
          const float* __restrict__ w1s, const float* __restrict__ b1s,
          const float* __restrict__ w2s, const float* __restrict__ b2s,
          const float* __restrict__ w3s, const float* __restrict__ b3s,
          const float* __restrict__ w1t, const float* __restrict__ b1t,
          const float* __restrict__ w2t, const float* __restrict__ b2t,
          const float* __restrict__ w3t, const float* __restrict__ b3t,
          float* __restrict__ out)
{
    constexpr bool FIRST = (LYR == 0);
    constexpr bool LAST  = (LYR == 3);
    // KEEP = ((0,1),(1,2),(2,3),(0,3)); TRANS = ((2,3),(0,3),(0,1),(1,2))
    constexpr int K0 = (LYR == 0) ? 0 : (LYR == 1) ? 1 : (LYR == 2) ? 2 : 0;
    constexpr int K1 = (LYR == 0) ? 1 : (LYR == 1) ? 2 : (LYR == 2) ? 3 : 3;
    constexpr int T0 = (LYR == 0) ? 2 : (LYR == 1) ? 0 : (LYR == 2) ? 0 : 1;
    constexpr int T1 = (LYR == 0) ? 3 : (LYR == 1) ? 3 : (LYR == 2) ? 1 : 2;

    extern __shared__ char smem[];
    const uint32_t smem_base = smem_u32(smem);
    __half* sW1 = reinterpret_cast<__half*>(smem + OFF_W1);
    __half* sW2 = reinterpret_cast<__half*>(smem + OFF_W2);
    __half* sW3 = reinterpret_cast<__half*>(smem + OFF_W3);
    uint32_t* sB1h = reinterpret_cast<uint32_t*>(smem + OFF_B1);  // 128 half2
    uint32_t* sB2h = reinterpret_cast<uint32_t*>(smem + OFF_B2);  // 128 half2
    float* sB3 = reinterpret_cast<float*>(smem + OFF_B3);

    const int tid = threadIdx.x;

    // ---- one-time weights -> smem ----
    // W1 rows: 0..63 = w1[k+2] (h part), 64..65 = w1[0..1] (x-keep), 66..79 = 0
    for (int idx = tid; idx < 80 * W_LD; idx += NTHREADS) {
        int k = idx / W_LD, c = idx - k * W_LD;
        float v = 0.0f;
        if (c < 256) {
            const float* w1 = (c < 128) ? w1s : w1t;
            int cc = c & 127;
            if (k < 64)      v = w1[(k + 2) * 128 + cc];
            else if (k < 66) v = w1[(k - 64) * 128 + cc];
        }
        sW1[idx] = __float2half(v);
    }
    for (int idx = tid; idx < 128 * W_LD; idx += NTHREADS) {
        int k = idx / W_LD, c = idx - k * W_LD;
        float v = 0.0f;
        if (c < 256) v = (c < 128) ? w2s[k * 128 + c] : w2t[k * 128 + c - 128];
        sW2[idx] = __float2half(v);
    }
    for (int idx = tid; idx < 128 * W3_LD; idx += NTHREADS) {
        int k = idx >> 4, c = idx & 15;
        float v = 0.0f;
        if (c < 2) v = w3s[k * 2 + c];
        else if (c >= 8 && c < 10) v = w3t[k * 2 + c - 8];
        sW3[idx] = __float2half(v);
    }
    for (int i = tid; i < 128; i += NTHREADS) {
        int c = i * 2;
        float a1 = (c < 128) ? b1s[c] : b1t[c - 128];
        float b1 = (c + 1 < 128) ? b1s[c + 1] : b1t[c + 1 - 128];
        sB1h[i] = pack_h2(a1, b1);
        float a2 = (c < 128) ? b2s[c] : b2t[c - 128];
        float b2 = (c + 1 < 128) ? b2s[c + 1] : b2t[c + 1 - 128];
        sB2h[i] = pack_h2(a2, b2);
    }
    if (tid < 4) sB3[tid] = (tid < 2) ? b3s[tid] : b3t[tid - 2];
    // zero xp pad cols [66,88) in BOTH buffers (never rewritten)
    for (int idx = tid; idx < 2 * 128 * 22; idx += NTHREADS) {
        int bufr = idx / 22, c = 66 + (idx - bufr * 22);
        int bb = bufr >> 7, r = bufr & 127;
        *reinterpret_cast<__half*>(
            smem + OFF_XP + bb * XP_BYTES + (r * XP_LD + c) * 2) = __float2half(0.0f);
    }

    const int warp = tid >> 5;
    const int lane = tid & 31;
    const int net  = warp >> 3;       // 0 = s-net (warps 0-7), 1 = t-net (8-15)
    const int R0   = (warp & 7) * 16; // row block
    const int lg   = lane >> 3;
    const int lr   = lane & 7;
    const int l4   = lane & 3;        // bias pair index offset

    // ---- prologue: prefetch tile0 into buf 0 ----
    const int tile0 = blockIdx.x;
    {
        const __half* hsrc = g_hh + (long)tile0 * MTILE * 64;
        uint32_t xpn = smem_base + OFF_XP;
        #pragma unroll
        for (int c = tid; c < 1024; c += NTHREADS) {
            int r = c >> 3, q = c & 7;
            cp_async16(xpn + r * 176 + q * 16, hsrc + r * 64 + q * 8);
        }
        if (tid < 128) {
            const float* xsrc = FIRST ? (theta + (long)(tile0 * MTILE + tid) * 4)
                                      : (g_x + (long)(tile0 * MTILE + tid) * 4);
            cp_async16(smem_base + OFF_XA + tid * 16, xsrc);
        }
        CP_COMMIT();
        CP_WAIT0();
        if (tid < 128) {
            float4 nx = *reinterpret_cast<float4*>(smem + OFF_XA + tid * 16);
            float c4[4] = {nx.x, nx.y, nx.z, nx.w};
            *reinterpret_cast<__half2*>(smem + OFF_XP + tid * 176 + 128) =
                __floats2half2_rn(c4[K0], c4[K1]);
        }
    }
    __syncthreads();

    int buf = 0;
    for (int tile = tile0; tile < NTILES; tile += gridDim.x) {
        const int base = tile * MTILE;
        const int nt = tile + gridDim.x;
        const bool has_next = (nt < NTILES);

        // ---- prefetch next tile into buf^1 ----
        if (has_next) {
            const __half* hsrc = g_hh + (long)nt * MTILE * 64;
            uint32_t xpn = smem_base + OFF_XP + (buf ^ 1) * XP_BYTES;
            #pragma unroll
            for (int c = tid; c < 1024; c += NTHREADS) {
                int r = c >> 3, q = c & 7;
                cp_async16(xpn + r * 176 + q * 16, hsrc + r * 64 + q * 8);
            }
            if (tid < 128) {
                const float* xsrc = FIRST ? (theta + (long)(nt * MTILE + tid) * 4)
                                          : (g_x + (long)(nt * MTILE + tid) * 4);
                cp_async16(smem_base + OFF_XA + (buf ^ 1) * 2048 + tid * 16, xsrc);
            }
            CP_COMMIT();
        }

        __half* sXP = reinterpret_cast<__half*>(smem + OFF_XP + buf * XP_BYTES);
        float* sST = reinterpret_cast<float*>(smem + OFF_ST + buf * 2048);

        // ---- GEMM1: A frags from xp (K=80) ----
        uint32_t axp[5][4];
        {
            int row = R0 + lr + (lg & 1) * 8;
            int colo = (lg >> 1) * 8;
            const __half* pbase = &sXP[row * XP_LD + colo];
            #pragma unroll
            for (int ks = 0; ks < 5; ks++) {
                ldsm_x4(smem_u32(pbase + ks * 16),
                        axp[ks][0], axp[ks][1], axp[ks][2], axp[ks][3]);
            }
        }
        // hid1 kept as 8 A-fragments (f16, K-local 0..127 of this net's half)
        uint32_t hfr[8][4];
        #pragma unroll
        for (int ch = 0; ch < 2; ch++) {
            uint32_t acc[8][2];
            #pragma unroll
            for (int j = 0; j < 8; j++) {   // bias init (packed half2)
                uint32_t bb = sB1h[net * 64 + ch * 32 + j * 4 + l4];
                acc[j][0] = bb; acc[j][1] = bb;
            }
            const __half* wb =
                &sW1[(lr + (lg & 1) * 8) * W_LD + net * 128 + ch * 64 + (lg >> 1) * 8];
            uint32_t bfa[4][4], bfb[4][4];
            ldB4(wb, bfa);
            ldB4(wb + 16 * W_LD, bfb);  mma8h(acc, axp[0], bfa);
            ldB4(wb + 32 * W_LD, bfa);  mma8h(acc, axp[1], bfb);
            ldB4(wb + 48 * W_LD, bfb);  mma8h(acc, axp[2], bfa);
            ldB4(wb + 64 * W_LD, bfa);  mma8h(acc, axp[3], bfb);
                                        mma8h(acc, axp[4], bfa);
            #pragma unroll
            for (int kf = 0; kf < 4; kf++) {   // gelu in place; regs ARE the A frags
                hfr[ch * 4 + kf][0] = gelu2h(acc[2 * kf][0]);
                hfr[ch * 4 + kf][1] = gelu2h(acc[2 * kf][1]);
                hfr[ch * 4 + kf][2] = gelu2h(acc[2 * kf + 1][0]);
                hfr[ch * 4 + kf][3] = gelu2h(acc[2 * kf + 1][1]);
            }
        }

        // ---- GEMM2 (+fused GEMM3), this warp's net ----
        float acc3[4] = {0.f, 0.f, 0.f, 0.f};
        #pragma unroll
        for (int cc = 0; cc < 2; cc++) {
            uint32_t acc[8][2];
            #pragma unroll
            for (int j = 0; j < 8; j++) {
                uint32_t bb = sB2h[net * 64 + cc * 32 + j * 4 + l4];
                acc[j][0] = bb; acc[j][1] = bb;
            }
            const __half* wb =
                &sW2[(lr + (lg & 1) * 8) * W_LD + net * 128 + cc * 64 + (lg >> 1) * 8];
            uint32_t bfa[4][4], bfb[4][4];
            ldB4(wb, bfa);
            ldB4(wb +  16 * W_LD, bfb);  mma8h(acc, hfr[0], bfa);
            ldB4(wb +  32 * W_LD, bfa);  mma8h(acc, hfr[1], bfb);
            ldB4(wb +  48 * W_LD, bfb);  mma8h(acc, hfr[2], bfa);
            ldB4(wb +  64 * W_LD, bfa);  mma8h(acc, hfr[3], bfb);
            ldB4(wb +  80 * W_LD, bfb);  mma8h(acc, hfr[4], bfa);
            ldB4(wb +  96 * W_LD, bfa);  mma8h(acc, hfr[5], bfb);
            ldB4(wb + 112 * W_LD, bfb);  mma8h(acc, hfr[6], bfa);
                                         mma8h(acc, hfr[7], bfb);
            uint32_t af[4][4];
            #pragma unroll
            for (int kf = 0; kf < 4; kf++) {
                af[kf][0] = gelu2h(acc[2 * kf][0]);
                af[kf][1] = gelu2h(acc[2 * kf][1]);
                af[kf][2] = gelu2h(acc[2 * kf + 1][0]);
                af[kf][3] = gelu2h(acc[2 * kf + 1][1]);
            }
            // GEMM3 partial: hid2 chunk (K=64) x W3[net] (N=8, cols 0..1 valid)
            #pragma unroll
            for (int kf = 0; kf < 4; kf++) {
                int k0 = cc * 64 + kf * 16;
                uint32_t addr =
                    smem_u32(&sW3[(k0 + (lane & 15)) * W3_LD + net * 8]);
                uint32_t b0, b1;
                ldsm_x2t(addr, b0, b1);
                mma_hf32(acc3, af[kf], b0, b1);
            }
        }

        // ---- stage this net's (c0,c1) per row into smem ----
        if ((lane & 3) == 0) {
            int r1 = lane >> 2;
            #pragma unroll
            for (int half = 0; half < 2; half++) {
                int row = R0 + r1 + half * 8;
                sST[(net * 128 + row) * 2 + 0] = acc3[half * 2 + 0];
                sST[(net * 128 + row) * 2 + 1] = acc3[half * 2 + 1];
            }
        }

        // current-tile x into regs (sXA[buf] final since last iteration)
        float4 xv = make_float4(0.f, 0.f, 0.f, 0.f);
        if (tid < 128)
            xv = *reinterpret_cast<float4*>(smem + OFF_XA + buf * 2048 + tid * 16);

        // finish next-tile prefetch: wait + x-keep conversion into xp[buf^1]
        if (has_next) {
            CP_WAIT0();
            if (tid < 128) {
                float4 nx = *reinterpret_cast<float4*>(
                    smem + OFF_XA + (buf ^ 1) * 2048 + tid * 16);
                float c4[4] = {nx.x, nx.y, nx.z, nx.w};
                *reinterpret_cast<__half2*>(
                    smem + OFF_XP + (buf ^ 1) * XP_BYTES + tid * 176 + 128) =
                    __floats2half2_rn(c4[K0], c4[K1]);
            }
        }
        __syncthreads();

        // ---- epilogue: one thread per row ----
        if (tid < 128) {
            int row = tid;
            int b = base + row;
            float s0 = sST[row * 2 + 0] + sB3[0];
            float s1 = sST[row * 2 + 1] + sB3[1];
            float t0 = sST[(128 + row) * 2 + 0] + sB3[2];
            float t1 = sST[(128 + row) * 2 + 1] + sB3[3];
            float xc[4] = {xv.x, xv.y, xv.z, xv.w};
            float nx0 = xc[T0] * __expf(s0) + t0;
            float nx1 = xc[T1] * __expf(s1) + t1;
            float ld = s0 + s1;
            if (!FIRST) ld += g_ld[b];
            xc[T0] = nx0;
            xc[T1] = nx1;
            if (!LAST) {
                reinterpret_cast<float4*>(g_x)[b] =
                    make_float4(xc[0], xc[1], xc[2], xc[3]);
                g_ld[b] = ld;
            } else {
                float ss = xc[0] * xc[0] + xc[1] * xc[1] +
                           xc[2] * xc[2] + xc[3] * xc[3];
                out[b] = -0.5f * ss - 3.6757541328186907f + ld;
            }
        }
        buf ^= 1;
    }
}

extern "C" void kernel_launch(void* const* d_in, const int* in_sizes, int n_in,
                              void* d_out, int out_size)
{
    const float* theta = (const float*)d_in[0];
    const float* h     = (const float*)d_in[1];
    const float* sW1   = (const float*)d_in[2];
    const float* sb1   = (const float*)d_in[3];
    const float* sW2   = (const float*)d_in[4];
    const float* sb2   = (const float*)d_in[5];
    const float* sW3   = (const float*)d_in[6];
    const float* sb3   = (const float*)d_in[7];
    const float* tW1   = (const float*)d_in[8];
    const float* tb1   = (const float*)d_in[9];
    const float* tW2   = (const float*)d_in[10];
    const float* tb2   = (const float*)d_in[11];
    const float* tW3   = (const float*)d_in[12];
    const float* tb3   = (const float*)d_in[13];
    float* out = (float*)d_out;

    int nsm = 148;
    cudaDeviceGetAttribute(&nsm, cudaDevAttrMultiProcessorCount, 0);

    cudaFuncSetAttribute(nvp_layer<0>, cudaFuncAttributeMaxDynamicSharedMemorySize, SMEM_BYTES);
    cudaFuncSetAttribute(nvp_layer<1>, cudaFuncAttributeMaxDynamicSharedMemorySize, SMEM_BYTES);
    cudaFuncSetAttribute(nvp_layer<2>, cudaFuncAttributeMaxDynamicSharedMemorySize, SMEM_BYTES);
    cudaFuncSetAttribute(nvp_layer<3>, cudaFuncAttributeMaxDynamicSharedMemorySize, SMEM_BYTES);

    // pre-pass: h -> f16 (BTOT*64 elems, 8 per thread, 256 threads/block)
    cvt_h_kernel<<<(BTOT * 64) / (8 * 256), 256>>>(h);

    dim3 grid(nsm), blk(NTHREADS);
    #define ARGS(L) theta, h,                                        \
        sW1 + (L) * 66 * 128, sb1 + (L) * 128,                       \
        sW2 + (L) * 128 * 128, sb2 + (L) * 128,                      \
        sW3 + (L) * 128 * 2, sb3 + (L) * 2,                          \
        tW1 + (L) * 66 * 128, tb1 + (L) * 128,                       \
        tW2 + (L) * 128 * 128, tb2 + (L) * 128,                      \
        tW3 + (L) * 128 * 2, tb3 + (L) * 2, out

    nvp_layer<0><<<grid, blk, SMEM_BYTES>>>(ARGS(0));
    nvp_layer<1><<<grid, blk, SMEM_BYTES>>>(ARGS(1));
    nvp_layer<2><<<grid, blk, SMEM_BYTES>>>(ARGS(2));
    nvp_layer<3><<<grid, blk, SMEM_BYTES>>>(ARGS(3));
    #undef ARGS
}